// round 16
// baseline (speedup 1.0000x reference)
#include <cuda_runtime.h>

#define P 45
#define PP (P * P)              // 2025
#define BPB 4
#define TPB (BPB * 32)          // 128 threads, 1 warp per batch
#define NITER 20
#define PPAD 48

// Shared: sig_sh[BPB][2025] contiguous, w_sh[BPB][PPAD]
#define SMEM_FLOATS (BPB * PP + BPB * PPAD)

typedef unsigned long long ull;

__device__ __forceinline__ void ffma2(ull& d, ull a, ull b) {
    asm("fma.rn.f32x2 %0, %1, %2, %0;" : "+l"(d) : "l"(a), "l"(b));
}
__device__ __forceinline__ ull fadd2(ull a, ull b) {
    ull d;
    asm("add.rn.f32x2 %0, %1, %2;" : "=l"(d) : "l"(a), "l"(b));
    return d;
}
__device__ __forceinline__ float f2sum(ull a) {
    float lo, hi;
    asm("mov.b64 {%0,%1},%2;" : "=f"(lo), "=f"(hi) : "l"(a));
    return lo + hi;
}
__device__ __forceinline__ ull pk(float lo, float hi) {
    ull d;
    asm("mov.b64 %0,{%1,%2};" : "=l"(d) : "f"(lo), "f"(hi));
    return d;
}
__device__ __forceinline__ void lds_v2u64(ull& a, ull& b, unsigned saddr) {
    asm volatile("ld.shared.v2.b64 {%0,%1},[%2];" : "=l"(a), "=l"(b) : "r"(saddr));
}
__device__ __forceinline__ float frcp(float x) {
    float r;
    asm("rcp.approx.f32 %0, %1;" : "=f"(r) : "f"(x));
    return r;
}
// Warp sum via integer redux (sm_103 has no redux.f32). x in [0, ~0.3].
__device__ __forceinline__ float qsum(float x) {
    int xi = __float2int_rn(x * 134217728.0f);          // 2^27
    int s  = __reduce_add_sync(0xffffffffu, xi);
    return (float)s * 7.450580596923828e-9f;            // 2^-27
}

__global__ __launch_bounds__(TPB, 5)
void drb_kernel(const float* __restrict__ sigma,
                const float* __restrict__ beta,
                const float* __restrict__ wprev,
                const float* __restrict__ lls,
                const float* __restrict__ llt,
                float* __restrict__ out,
                int B)
{
    extern __shared__ float sh[];
    float* w_sh = sh + BPB * PP;         // [BPB][PPAD]

    const int t    = threadIdx.x;
    const int warp = t >> 5;
    const int lane = t & 31;
    const int a    = lane >> 1;
    const int odd  = lane & 1;
    const int r0   = 3 * a + odd;        // owned row (0..46)
    const int r2   = 3 * a + 2;          // odd-owned row (2..47)
    const bool rows_ok = (a < 15);
    const bool act0 = (r0 < P);
    const bool act2 = (r2 < P) && odd;

    float* sig_w = sh + warp * PP;
    const unsigned sdst = (unsigned)__cvta_generic_to_shared(sig_w);

    const int stride = gridDim.x * BPB;
    int b = blockIdx.x * BPB + warp;

    const float lam_s  = expf(lls[0]);
    const float lam_t2 = 2.f * expf(llt[0]);
    const float k_w    = 1.f - 0.05f * lam_t2;
    const float d_s    = 0.05f * lam_s;

    // ---- stage batch bb's sigma into my smem slice (async, one group) ----
    auto stage = [&](int bb) {
        const float* gsrc = sigma + (size_t)bb * PP;
        const int mis = (int)(((size_t)bb * PP) & 3);
        const int h   = (4 - mis) & 3;
        if (lane < h) {
            asm volatile("cp.async.ca.shared.global [%0], [%1], 4;"
                         :: "r"(sdst + lane * 4), "l"(gsrc + lane));
        }
        const int n4 = (PP - h) >> 2;
        const float* gb = gsrc + h;
        const unsigned sb = sdst + h * 4;
        for (int i = lane; i < n4; i += 32) {
            asm volatile("cp.async.cg.shared.global [%0], [%1], 16;"
                         :: "r"(sb + i * 16), "l"(gb + i * 4));
        }
        const int tl = (PP - h) & 3;
        if (lane < tl) {
            asm volatile("cp.async.ca.shared.global [%0], [%1], 4;"
                         :: "r"(sb + n4 * 16 + lane * 4), "l"(gb + n4 * 4 + lane));
        }
        asm volatile("cp.async.commit_group;");
    };

    if (b < B) stage(b);

    const unsigned wsa_h =
        (unsigned)__cvta_generic_to_shared(&w_sh[warp * PPAD]) + odd * 96;

    for (; b < B; b += stride) {
        // ---- issue beta/wprev LDGs early (overlap with cp.async wait) ----
        float beta0 = 0.f, wp0 = 0.f, beta2 = 0.f, wp2 = 0.f;
        if (act0) {
            beta0 = beta[(size_t)b * P + r0];
            wp0   = wprev[(size_t)b * P + r0];
        }
        if (act2) {
            beta2 = beta[(size_t)b * P + r2];
            wp2   = wprev[(size_t)b * P + r2];
        }

        asm volatile("cp.async.wait_group 0;");
        __syncwarp();

        // ---- fill sigma registers (sig_w is dead afterwards) ----
        ull sA[12], sB[12], sC[12];
        #pragma unroll
        for (int i = 0; i < 3; i++) {
            ull* dst = (i == 0) ? sA : (i == 1) ? sB : sC;
            const float* base = sig_w + (3 * a + i) * P + odd * 24;
            if (rows_ok) {
                if (odd) {   // cols 24..44 (21 floats), then zeros
                    #pragma unroll
                    for (int j = 0; j < 10; j++) dst[j] = pk(base[2 * j], base[2 * j + 1]);
                    dst[10] = pk(base[20], 0.f);
                    dst[11] = 0ull;
                } else {     // cols 0..23
                    #pragma unroll
                    for (int j = 0; j < 12; j++) dst[j] = pk(base[2 * j], base[2 * j + 1]);
                }
            } else {
                #pragma unroll
                for (int j = 0; j < 12; j++) dst[j] = 0ull;
            }
        }

        // ---- prefetch NEXT batch into the (now dead) smem slice ----
        int bn = b + stride;
        if (bn < B) stage(bn);

        const float c_b0 = 0.05f * fmaf(lam_t2, wp0, beta0);
        const float c_b2 = 0.05f * fmaf(lam_t2, wp2, beta2);

        float w0 = act0 ? (1.f / (float)P) : 0.f;
        float w2 = act2 ? (1.f / (float)P) : 0.f;
        w_sh[warp * PPAD + r0] = w0;
        if (odd) w_sh[warp * PPAD + r2] = w2;
        __syncwarp();

        for (int it = 0; it < NITER; it++) {
            // ---- half-dots for rows A=3a, B=3a+1, C=3a+2 over my 24 cols ----
            ull aA0 = 0ull, aA1 = 0ull, aB0 = 0ull, aB1 = 0ull, aC0 = 0ull, aC1 = 0ull;
            #pragma unroll
            for (int k = 0; k < 6; k++) {
                ull wv0, wv1;
                lds_v2u64(wv0, wv1, wsa_h + 16 * k);
                ffma2(aA0, sA[2 * k],     wv0);
                ffma2(aA1, sA[2 * k + 1], wv1);
                ffma2(aB0, sB[2 * k],     wv0);
                ffma2(aB1, sB[2 * k + 1], wv1);
                ffma2(aC0, sC[2 * k],     wv0);
                ffma2(aC1, sC[2 * k + 1], wv1);
            }
            float pA = f2sum(fadd2(aA0, aA1));
            float pB = f2sum(fadd2(aB0, aB1));
            float pC = f2sum(fadd2(aC0, aC1));

            // ---- combine halves across lane pair (2 shfl, merged) ----
            float mine = odd ? pB : pA;
            float send = odd ? pA : pB;
            float Sw0 = mine + __shfl_xor_sync(0xffffffffu, send, 1);
            float Sw2 = pC + __shfl_xor_sync(0xffffffffu, pC, 1);

            // ---- folded gradient step + first clip ----
            float cs0 = (w0 > 0.f) ? (c_b0 - d_s) : c_b0;
            float v0 = fmaf(k_w, w0, fmaf(-0.1f, Sw0, cs0));
            v0 = fminf(fmaxf(v0, 0.f), 0.15f);
            float cs2 = (w2 > 0.f) ? (c_b2 - d_s) : c_b2;
            float v2 = fmaf(k_w, w2, fmaf(-0.1f, Sw2, cs2));
            v2 = fminf(fmaxf(v2, 0.f), 0.15f);
            v2 = act2 ? v2 : 0.f;

            // ---- normalize #1 (integer redux warp sum) ----
            float s1 = qsum(v0 + v2);
            float inv1 = frcp(s1 + 1e-8f);
            float u0 = fminf(v0 * inv1, 0.15f);
            float u2 = fminf(v2 * inv1, 0.15f);

            // ---- normalize #2 ----
            float s2 = qsum(u0 + u2);
            float inv2 = frcp(s2 + 1e-8f);
            w0 = u0 * inv2;
            w2 = u2 * inv2;

            w_sh[warp * PPAD + r0] = w0;
            if (odd) w_sh[warp * PPAD + r2] = w2;
            __syncwarp();
        }

        if (act0) out[(size_t)b * P + r0] = w0;
        if (act2) out[(size_t)b * P + r2] = w2;
    }
}

extern "C" void kernel_launch(void* const* d_in, const int* in_sizes, int n_in,
                              void* d_out, int out_size)
{
    const float* sigma = (const float*)d_in[0];
    const float* beta  = (const float*)d_in[1];
    const float* wprev = (const float*)d_in[2];
    const float* lls   = (const float*)d_in[3];
    const float* llt   = (const float*)d_in[4];
    float* out = (float*)d_out;

    int B = in_sizes[1] / P;
    int need = (B + BPB - 1) / BPB;
    int grid = 148 * 5;                  // one full wave of persistent blocks
    if (grid > need) grid = need;
    size_t smem = SMEM_FLOATS * sizeof(float);

    drb_kernel<<<grid, TPB, smem>>>(sigma, beta, wprev, lls, llt, out, B);
}

// round 17
// speedup vs baseline: 1.5334x; 1.5334x over previous
#include <cuda_runtime.h>

#define P 45
#define PP (P * P)              // 2025
#define BPB 4
#define TPB (BPB * 32)          // 128 threads, 1 warp per batch
#define NITER 20
#define PPAD 48

// Shared: sig_sh[BPB][2025] contiguous, w_sh[BPB][PPAD]
#define SMEM_FLOATS (BPB * PP + BPB * PPAD)

typedef unsigned long long ull;

__device__ __forceinline__ void ffma2(ull& d, ull a, ull b) {
    asm("fma.rn.f32x2 %0, %1, %2, %0;" : "+l"(d) : "l"(a), "l"(b));
}
__device__ __forceinline__ ull fadd2(ull a, ull b) {
    ull d;
    asm("add.rn.f32x2 %0, %1, %2;" : "=l"(d) : "l"(a), "l"(b));
    return d;
}
__device__ __forceinline__ float f2sum(ull a) {
    float lo, hi;
    asm("mov.b64 {%0,%1},%2;" : "=f"(lo), "=f"(hi) : "l"(a));
    return lo + hi;
}
__device__ __forceinline__ ull pk(float lo, float hi) {
    ull d;
    asm("mov.b64 %0,{%1,%2};" : "=l"(d) : "f"(lo), "f"(hi));
    return d;
}
__device__ __forceinline__ void lds_v2u64(ull& a, ull& b, unsigned saddr) {
    asm volatile("ld.shared.v2.b64 {%0,%1},[%2];" : "=l"(a), "=l"(b) : "r"(saddr));
}
__device__ __forceinline__ float frcp(float x) {
    float r;
    asm("rcp.approx.f32 %0, %1;" : "=f"(r) : "f"(x));
    return r;
}
// Warp sum in 2^-20 fixed point, float<->int via 2^23 magic number
// (FFMA/IADD instead of F2I/I2F). Returns integer-valued float = sum * 2^20.
// Valid: per-lane x in [0, 8); warp total < 8 (so int sum < 2^23).
__device__ __forceinline__ float qsum20(float x) {
    int xi = __float_as_int(fmaf(x, 1048576.0f, 8388608.0f)) - 0x4B000000;
    int s  = __reduce_add_sync(0xffffffffu, xi);
    return __int_as_float(s + 0x4B000000) - 8388608.0f;
}

__global__ __launch_bounds__(TPB, 5)
void drb_kernel(const float* __restrict__ sigma,
                const float* __restrict__ beta,
                const float* __restrict__ wprev,
                const float* __restrict__ lls,
                const float* __restrict__ llt,
                float* __restrict__ out,
                int B)
{
    extern __shared__ float sh[];
    float* sig_sh = sh;                  // [BPB][2025] contiguous
    float* w_sh   = sh + BPB * PP;       // [BPB][PPAD]

    const int t    = threadIdx.x;
    const int warp = t >> 5;             // batch-in-block
    const int lane = t & 31;
    const int a    = lane >> 1;
    const int odd  = lane & 1;
    const int r0   = 3 * a + odd;        // owned row for w0-chain (0..46)
    const int r2   = 3 * a + 2;          // odd-owned row (2..47)
    const int batch = blockIdx.x * BPB + warp;

    // ---- Per-warp async staging with 16B cp.async (alignment-aware) ----
    float* sig_w = sig_sh + warp * PP;
    unsigned sdst = (unsigned)__cvta_generic_to_shared(sig_w);
    if (batch < B) {
        const float* gsrc = sigma + (size_t)batch * PP;
        const int mis = (int)(((size_t)batch * PP) & 3);  // misalign in floats
        const int h   = (4 - mis) & 3;                    // head floats
        if (lane < h) {
            asm volatile("cp.async.ca.shared.global [%0], [%1], 4;"
                         :: "r"(sdst + lane * 4), "l"(gsrc + lane));
        }
        const int n4 = (PP - h) >> 2;
        const float* gb = gsrc + h;
        const unsigned sb = sdst + h * 4;
        for (int i = lane; i < n4; i += 32) {
            asm volatile("cp.async.cg.shared.global [%0], [%1], 16;"
                         :: "r"(sb + i * 16), "l"(gb + i * 4));
        }
        const int tl = (PP - h) & 3;
        if (lane < tl) {
            asm volatile("cp.async.ca.shared.global [%0], [%1], 4;"
                         :: "r"(sb + n4 * 16 + lane * 4), "l"(gb + n4 * 4 + lane));
        }
        asm volatile("cp.async.commit_group;");
    }

    // ---- Overlap: load beta/wprev while cp.async is in flight ----
    const bool act0 = (r0 < P);
    const bool act2 = (r2 < P) && odd;
    float beta0 = 0.f, wp0 = 0.f, beta2 = 0.f, wp2 = 0.f;
    if (batch < B) {
        if (act0) {
            beta0 = beta[(size_t)batch * P + r0];
            wp0   = wprev[(size_t)batch * P + r0];
        }
        if (act2) {
            beta2 = beta[(size_t)batch * P + r2];
            wp2   = wprev[(size_t)batch * P + r2];
        }
    }
    const float lam_s  = expf(lls[0]);
    const float lam_t2 = 2.f * expf(llt[0]);
    const float k_w    = 1.f - 0.05f * lam_t2;
    const float d_s    = 0.05f * lam_s;
    // Inactive lanes: c_b = -1e30 makes v clamp to 0 with no per-iter select.
    float c_b0 = act0 ? (0.05f * fmaf(lam_t2, wp0, beta0)) : -1e30f;
    float c_b2 = act2 ? (0.05f * fmaf(lam_t2, wp2, beta2)) : -1e30f;

    asm volatile("cp.async.wait_group 0;");
    __syncwarp();

    // ---- Fill sigma registers: MY HALF (24 cols) of rows 3a, 3a+1, 3a+2 ----
    // even lane: cols 0..23 ; odd lane: cols 24..47 (45..47 zero)
    ull sA[12], sB[12], sC[12];
    {
        const bool rows_ok = (a < 15);   // a==15 -> rows 45..47 don't exist
        #pragma unroll
        for (int i = 0; i < 3; i++) {
            ull* dst = (i == 0) ? sA : (i == 1) ? sB : sC;
            const float* base = sig_w + (3 * a + i) * P + odd * 24;
            if (rows_ok) {
                if (odd) {   // cols 24..44 real (21), then zeros
                    #pragma unroll
                    for (int j = 0; j < 10; j++) dst[j] = pk(base[2 * j], base[2 * j + 1]);
                    dst[10] = pk(base[20], 0.f);
                    dst[11] = 0ull;
                } else {     // cols 0..23
                    #pragma unroll
                    for (int j = 0; j < 12; j++) dst[j] = pk(base[2 * j], base[2 * j + 1]);
                }
            } else {
                #pragma unroll
                for (int j = 0; j < 12; j++) dst[j] = 0ull;
            }
        }
    }

    float w0 = act0 ? (1.f / (float)P) : 0.f;
    float w2 = act2 ? (1.f / (float)P) : 0.f;
    w_sh[warp * PPAD + r0] = w0;          // covers rows {3a, 3a+1}
    if (odd) w_sh[warp * PPAD + r2] = w2; // covers rows {3a+2}
    const unsigned wsa_h =
        (unsigned)__cvta_generic_to_shared(&w_sh[warp * PPAD]) + odd * 96;
    __syncwarp();

    for (int it = 0; it < NITER; it++) {
        // ---- half-dots for rows A=3a, B=3a+1, C=3a+2 over my 24 cols ----
        ull aA0 = 0ull, aA1 = 0ull, aB0 = 0ull, aB1 = 0ull, aC0 = 0ull, aC1 = 0ull;
        #pragma unroll
        for (int k = 0; k < 6; k++) {
            ull wv0, wv1;
            lds_v2u64(wv0, wv1, wsa_h + 16 * k);
            ffma2(aA0, sA[2 * k],     wv0);
            ffma2(aA1, sA[2 * k + 1], wv1);
            ffma2(aB0, sB[2 * k],     wv0);
            ffma2(aB1, sB[2 * k + 1], wv1);
            ffma2(aC0, sC[2 * k],     wv0);
            ffma2(aC1, sC[2 * k + 1], wv1);
        }
        float pA = f2sum(fadd2(aA0, aA1));
        float pB = f2sum(fadd2(aB0, aB1));
        float pC = f2sum(fadd2(aC0, aC1));

        // ---- combine halves across lane pair (2 shfl, merged exchange) ----
        float mine = odd ? pB : pA;
        float send = odd ? pA : pB;
        float Sw0 = mine + __shfl_xor_sync(0xffffffffu, send, 1);
        float Sw2 = pC + __shfl_xor_sync(0xffffffffu, pC, 1);

        // ---- folded gradient step + first clip ----
        float cs0 = (w0 > 0.f) ? (c_b0 - d_s) : c_b0;
        float v0 = fmaf(k_w, w0, fmaf(-0.1f, Sw0, cs0));
        v0 = fminf(fmaxf(v0, 0.f), 0.15f);
        float cs2 = (w2 > 0.f) ? (c_b2 - d_s) : c_b2;
        float v2 = fmaf(k_w, w2, fmaf(-0.1f, Sw2, cs2));
        v2 = fminf(fmaxf(v2, 0.f), 0.15f);

        // ---- normalize #1 folded into a clip-at-threshold:
        //      u_i = min(v_i/s1p, .15)  =>  w_i = m_i / (sum(m) + eps),
        //      m_i = min(v_i, .15*s1p). Skips one rcp + two muls. ----
        float s1i = qsum20(v0 + v2);                       // = s1 * 2^20
        float thresh = fmaf(s1i, 1.430511474609375e-7f,    // 0.15*2^-20
                            1.5e-9f);                      // 0.15*1e-8
        float m0 = fminf(v0, thresh);
        float m2 = fminf(v2, thresh);

        // ---- normalize #2 ----
        float s2i = qsum20(m0 + m2);                       // = sum(m) * 2^20
        float inv = frcp(fmaf(s2i, 9.5367431640625e-7f, 1e-8f));
        w0 = m0 * inv;
        w2 = m2 * inv;

        w_sh[warp * PPAD + r0] = w0;
        if (odd) w_sh[warp * PPAD + r2] = w2;
        __syncwarp();
    }

    if (batch < B) {
        if (act0) out[(size_t)batch * P + r0] = w0;
        if (act2) out[(size_t)batch * P + r2] = w2;
    }
}

extern "C" void kernel_launch(void* const* d_in, const int* in_sizes, int n_in,
                              void* d_out, int out_size)
{
    const float* sigma = (const float*)d_in[0];
    const float* beta  = (const float*)d_in[1];
    const float* wprev = (const float*)d_in[2];
    const float* lls   = (const float*)d_in[3];
    const float* llt   = (const float*)d_in[4];
    float* out = (float*)d_out;

    int B = in_sizes[1] / P;
    int grid = (B + BPB - 1) / BPB;
    size_t smem = SMEM_FLOATS * sizeof(float);

    drb_kernel<<<grid, TPB, smem>>>(sigma, beta, wprev, lls, llt, out, B);
}